// round 7
// baseline (speedup 1.0000x reference)
#include <cuda_runtime.h>
#include <cstdint>

// Problem constants
#define SEQ    512
#define BATCH  64
#define INDIM  128
#define HDIM   512

// Tiling: 16 j-tiles x 8 b-tiles = 128 CTAs (one per SM; 128 < 148 SMs -> all resident)
#define JT     32            // h-columns per CTA
#define BT     8             // batch rows per CTA
#define NJ     (HDIM / JT)   // 16 j-tiles (producers per batch group)
#define NB     (BATCH / BT)  // 8 batch groups
#define NCTA   (NJ * NB)     // 128
#define THREADS 256
#define NWARP   8

// K-chunks (float4 granularity) per warp
#define WH_CPW ((HDIM / 4) / NWARP)   // 16
#define WI_CPW ((INDIM / 4) / NWARP)  // 4

// smem layout (float offsets). Padded row strides -> conflict-free STS/LDS.
#define N_WH   (HDIM * JT)            // 16384
#define N_WI   (INDIM * JT)           // 4096
#define H_STR4 132                    // float4 stride per h row (128 + 4 pad)
#define N_H    (BT * H_STR4 * 4)      // 4224
#define X_STR4 36                     // float4 stride per x row (32 + 4 pad)
#define N_X    (BT * X_STR4 * 4)      // 1152
#define RED_STRIDE 73
#define N_RED  (32 * RED_STRIDE)      // 2336
#define SMEM_FLOATS (N_WH + N_WI + N_H + N_X + N_RED)
#define SMEM_BYTES  (SMEM_FLOATS * 4) // ~113 KB

// Safety bound on spin iterations (unreachable in any correct run; converts a
// pathological stall into a fast wrong-answer instead of a container-killing hang)
#define SPIN_LIMIT (1u << 27)

// Per-batch-group cumulative step flags, 128B apart.
// Reset via cudaMemsetAsync every kernel_launch (graph-safe, replay-safe).
__device__ unsigned g_flags[NB * 32];

// Packed dual-FMA: acc.{lo,hi} += a.{lo,hi} * b.{lo,hi}
#define FMA2(acc, a, b) \
    asm("fma.rn.f32x2 %0, %1, %2, %0;" : "+l"(acc) : "l"(a), "l"(b))

__global__ __launch_bounds__(THREADS, 1)
void rnn_warpsync_kernel(const float* __restrict__ x,
                         const float* __restrict__ Wi,
                         const float* __restrict__ bi,
                         const float* __restrict__ Wh,
                         const float* __restrict__ bh,
                         float* __restrict__ out)
{
    extern __shared__ float smem[];
    float* sWh  = smem;                 // packed [kc][lane][4], conflict-free LDS.128
    float* sWi  = sWh + N_WH;
    float* sh   = sWi + N_WI;           // [b][kc] rows, stride H_STR4 float4
    float* sx   = sh  + N_H;            // [b][kc] rows, stride X_STR4 float4
    float* sred = sx  + N_X;            // [j][b*8+w], row stride 73

    const int tid  = threadIdx.x;
    const int bx   = blockIdx.x;
    const int bt   = bx / NJ;           // batch group
    const int jt   = bx % NJ;           // j tile
    const int j0   = jt * JT;
    const int b0   = bt * BT;
    const int lane = tid & 31;          // compute role: j within tile
    const int w    = tid >> 5;          // warp = K-slice owner; reduce role: batch
    const int lb   = lane >> 2;         // staging role: batch (0..7)
    const int lq   = lane & 3;          // staging role: quad within 16-float group

    // ---- One-time weight staging: Wh[j0+jj][k] -> sWh[(k>>2)*128 + jj*4 + (k&3)]
    for (int idx = tid; idx < JT * HDIM; idx += THREADS) {
        int jj = idx >> 9;
        int k  = idx & (HDIM - 1);
        sWh[(k >> 2) * (JT * 4) + jj * 4 + (k & 3)] = Wh[(j0 + jj) * HDIM + k];
    }
    for (int idx = tid; idx < JT * INDIM; idx += THREADS) {
        int jj = idx >> 7;
        int k  = idx & (INDIM - 1);
        sWi[(k >> 2) * (JT * 4) + jj * 4 + (k & 3)] = Wi[(j0 + jj) * INDIM + k];
    }
    const float cb = bi[j0 + lane] + bh[j0 + lane];
    __syncthreads();

    const ulonglong2* sWh2 = (const ulonglong2*)sWh;
    const ulonglong2* sWi2 = (const ulonglong2*)sWi;
    const ulonglong2* sh2  = (const ulonglong2*)sh;
    const ulonglong2* sx2  = (const ulonglong2*)sx;
    unsigned* flag = &g_flags[bt * 32];

    // x prefetch: warp w stages its Wi K-slice, 1 float4/lane: (b=lb, kc=w*4+lq)
    const float4* xsrc = (const float4*)x;
    float4 xr = xsrc[(size_t)0 * (BATCH * INDIM / 4) + (b0 + lb) * (INDIM / 4) + w * 4 + lq];

    for (int t = 0; t < SEQ; t++) {
        // Stage x[t] (per-warp region, conflict-free; consumed only by this warp)
        ((float4*)sx)[lb * X_STR4 + w * WI_CPW + lq] = xr;

        unsigned long long acc2[BT];
        #pragma unroll
        for (int b = 0; b < BT; b++) acc2[b] = 0ull;

        if (t > 0) {
            // ---- Per-warp acquire-poll with nanosleep backoff (bounded spin)
            if (lane == 0) {
                const unsigned target = (unsigned)(NJ * t);
                unsigned v, it = 0;
                while (true) {
                    asm volatile("ld.acquire.gpu.global.u32 %0, [%1];"
                                 : "=r"(v) : "l"(flag) : "memory");
                    if (v >= target || ++it >= SPIN_LIMIT) break;
                    __nanosleep(64);   // throttle L2 probes on the shared flag line
                }
            }
            __syncwarp();
            // Issue h K-slice loads (kc = w*16 + lq + 4i, all 8 batches; 64B runs)
            const float4* hsrc =
                (const float4*)(out + (size_t)(t - 1) * BATCH * HDIM);
            float4 hv0 = hsrc[(b0 + lb) * (HDIM / 4) + w * WH_CPW + lq + 0];
            float4 hv1 = hsrc[(b0 + lb) * (HDIM / 4) + w * WH_CPW + lq + 4];
            float4 hv2 = hsrc[(b0 + lb) * (HDIM / 4) + w * WH_CPW + lq + 8];
            float4 hv3 = hsrc[(b0 + lb) * (HDIM / 4) + w * WH_CPW + lq + 12];

            // ---- Wi partials overlap the h-LDG latency (no h dependence)
            {
                const int c0 = w * WI_CPW;
                #pragma unroll
                for (int c = 0; c < WI_CPW; c++) {
                    const int kc = c0 + c;
                    ulonglong2 wv = sWi2[kc * JT + lane];        // conflict-free
                    #pragma unroll
                    for (int b = 0; b < BT; b++) {
                        ulonglong2 hv = sx2[b * X_STR4 + kc];    // broadcast
                        FMA2(acc2[b], wv.x, hv.x);
                        FMA2(acc2[b], wv.y, hv.y);
                    }
                }
            }

            // Land h into smem (per-warp region), then consume
            float4* hdst = (float4*)sh + lb * H_STR4 + w * WH_CPW + lq;
            hdst[0]  = hv0;
            hdst[4]  = hv1;
            hdst[8]  = hv2;
            hdst[12] = hv3;
            __syncwarp();

            // Prefetch x[t+1] (latency hidden under Wh compute)
            if (t + 1 < SEQ)
                xr = xsrc[(size_t)(t + 1) * (BATCH * INDIM / 4)
                          + (b0 + lb) * (INDIM / 4) + w * 4 + lq];

            // ---- Wh partials: warp's K-slice, all 8 batches, 32 j (lanes)
            const int c0 = w * WH_CPW;
            #pragma unroll 4
            for (int c = 0; c < WH_CPW; c++) {
                const int kc = c0 + c;
                ulonglong2 wv = sWh2[kc * JT + lane];
                #pragma unroll
                for (int b = 0; b < BT; b++) {
                    ulonglong2 hv = sh2[b * H_STR4 + kc];        // broadcast
                    FMA2(acc2[b], wv.x, hv.x);
                    FMA2(acc2[b], wv.y, hv.y);
                }
            }
        } else {
            // t == 0: h is zero, only Wi part
            const int c0 = w * WI_CPW;
            #pragma unroll
            for (int c = 0; c < WI_CPW; c++) {
                const int kc = c0 + c;
                ulonglong2 wv = sWi2[kc * JT + lane];
                #pragma unroll
                for (int b = 0; b < BT; b++) {
                    ulonglong2 hv = sx2[b * X_STR4 + kc];
                    FMA2(acc2[b], wv.x, hv.x);
                    FMA2(acc2[b], wv.y, hv.y);
                }
            }
            xr = xsrc[(size_t)1 * (BATCH * INDIM / 4)
                      + (b0 + lb) * (INDIM / 4) + w * 4 + lq];
        }

        // Spill partials: sred[j][b*8+w] (stride 73 -> conflict-free)
        #pragma unroll
        for (int b = 0; b < BT; b++) {
            union { unsigned long long u; float2 f; } c; c.u = acc2[b];
            sred[lane * RED_STRIDE + b * NWARP + w] = c.f.x + c.f.y;
        }
        __syncthreads();                                   // bar 1: spill -> read

        // ---- Reduce 8 warp-partials (reduce role: b = w, j = lane), tanh, store
        {
            const float* r = &sred[lane * RED_STRIDE + w * NWARP];
            float s = ((r[0] + r[1]) + (r[2] + r[3])) + ((r[4] + r[5]) + (r[6] + r[7]));
            const float val = tanhf(cb + s);
            out[(size_t)t * BATCH * HDIM + (b0 + w) * HDIM + j0 + lane] = val;
            if (t == SEQ - 1)   // h_last appended after h_seq
                out[(size_t)SEQ * BATCH * HDIM + (b0 + w) * HDIM + j0 + lane] = val;
        }
        __syncthreads();                                   // bar 2: stores done, sred reusable
        if (tid == 0) {        // single release-publish (bar gives CTA happens-before,
                               // release is cumulative -> publishes all threads' stores)
            asm volatile("red.release.gpu.global.add.u32 [%0], %1;"
                         :: "l"(flag), "r"(1u) : "memory");
        }
    }
}

extern "C" void kernel_launch(void* const* d_in, const int* in_sizes, int n_in,
                              void* d_out, int out_size)
{
    const float* x  = (const float*)d_in[0];
    const float* Wi = (const float*)d_in[1];
    const float* bi = (const float*)d_in[2];
    const float* Wh = (const float*)d_in[3];
    const float* bh = (const float*)d_in[4];
    float* out = (float*)d_out;

    (void)in_sizes; (void)n_in; (void)out_size;

    void* flagsPtr = nullptr;
    cudaGetSymbolAddress(&flagsPtr, g_flags);
    cudaMemsetAsync(flagsPtr, 0, sizeof(g_flags), 0);

    cudaFuncSetAttribute(rnn_warpsync_kernel,
                         cudaFuncAttributeMaxDynamicSharedMemorySize, SMEM_BYTES);
    rnn_warpsync_kernel<<<NCTA, THREADS, SMEM_BYTES>>>(x, Wi, bi, Wh, bh, out);
}